// round 16
// baseline (speedup 1.0000x reference)
#include <cuda_runtime.h>
#include <cuda_fp16.h>
#include <stdint.h>
#include <math.h>

// Problem constants
static constexpr int Bc   = 2;
static constexpr int Sc   = 2048;
static constexpr int Dc   = 768;
static constexpr int Hc   = 12;
static constexpr int DKc  = 64;
static constexpr int DFFc = 3072;
static constexpr int Mc   = Bc * Sc;     // 4096 rows
static constexpr int QKVW = 3 * Dc;      // 2304 fused qkv width

// f32 scratch: two split-K partial slices, contiguous by construction
__device__ float g_tmp[2 * Mc * Dc];
__device__ float g_x1 [Mc * Dc];

// fp16 activations
__device__ __half g_xh  [Mc * Dc];
__device__ __half g_qkvh[Mc * QKVW];     // fused q|k|v, row stride 2304
__device__ __half g_ctxh[Mc * Dc];
__device__ __half g_x1h [Mc * Dc];
__device__ __half g_ff1h[Mc * DFFc];

// fp16 weights
__device__ __half g_wqkv[Dc * QKVW];     // wq|wk|wv fused, row stride 2304
__device__ float  g_bqkv[QKVW];          // bq|bk|bv fused
__device__ __half g_woh[Dc * Dc];
__device__ __half g_w1h[Dc * DFFc];
__device__ __half g_w2h[DFFc * Dc];

// ---------------------------------------------------------------------------
// helpers
// ---------------------------------------------------------------------------
__device__ __forceinline__ uint32_t sptr(const void* p) {
    return (uint32_t)__cvta_generic_to_shared(p);
}
__device__ __forceinline__ void ldsm4(uint32_t r[4], uint32_t addr) {
    asm volatile("ldmatrix.sync.aligned.m8n8.x4.shared.b16 {%0,%1,%2,%3},[%4];"
                 : "=r"(r[0]), "=r"(r[1]), "=r"(r[2]), "=r"(r[3]) : "r"(addr));
}
__device__ __forceinline__ void ldsm4t(uint32_t r[4], uint32_t addr) {
    asm volatile("ldmatrix.sync.aligned.m8n8.x4.trans.shared.b16 {%0,%1,%2,%3},[%4];"
                 : "=r"(r[0]), "=r"(r[1]), "=r"(r[2]), "=r"(r[3]) : "r"(addr));
}
__device__ __forceinline__ void mma16816h(float c[4], const uint32_t a[4],
                                          uint32_t b0, uint32_t b1) {
    asm volatile(
        "mma.sync.aligned.m16n8k16.row.col.f32.f16.f16.f32 "
        "{%0,%1,%2,%3},{%4,%5,%6,%7},{%8,%9},{%0,%1,%2,%3};"
        : "+f"(c[0]), "+f"(c[1]), "+f"(c[2]), "+f"(c[3])
        : "r"(a[0]), "r"(a[1]), "r"(a[2]), "r"(a[3]), "r"(b0), "r"(b1));
}
__device__ __forceinline__ void pack2h(float a, float b, uint32_t& h) {
    __half2 H; H.x = __float2half_rn(a); H.y = __float2half_rn(b);
    h = *(uint32_t*)&H;
}
__device__ __forceinline__ void cpasync16(const void* smem, const void* gmem) {
    asm volatile("cp.async.cg.shared.global [%0],[%1],16;"
                 :: "r"(sptr(smem)), "l"(gmem));
}
__device__ __forceinline__ void cpcommit() { asm volatile("cp.async.commit_group;"); }
template<int N>
__device__ __forceinline__ void cpwait() {
    asm volatile("cp.async.wait_group %0;" :: "n"(N));
}

// ---------------------------------------------------------------------------
// ONE fused conversion kernel: all weights, x, and bias concat.
// ---------------------------------------------------------------------------
static constexpr int CB_WQ   = Dc * Dc / 1024;            // 576
static constexpr int CB_WO   = CB_WQ;
static constexpr int CB_W1   = Dc * DFFc / 1024;          // 2304
static constexpr int CB_W2   = DFFc * Dc / 1024;          // 2304
static constexpr int CB_X    = Mc * Dc / 1024;            // 3072
static constexpr int CB_B0   = CB_WQ * 3;                 // 1728
static constexpr int CB_B1   = CB_B0 + CB_WO;             // 2304
static constexpr int CB_B2   = CB_B1 + CB_W1;             // 4608
static constexpr int CB_B3   = CB_B2 + CB_W2;             // 6912
static constexpr int CB_B4   = CB_B3 + CB_X;              // 9984
static constexpr int CB_TOTAL = CB_B4 + 1;                // + bias block

__device__ __forceinline__ void cvt4_to(const float* src, __half* dst, size_t i4) {
    float4 f = *(const float4*)(src + i4);
    __half hh[4] = {__float2half_rn(f.x), __float2half_rn(f.y),
                    __float2half_rn(f.z), __float2half_rn(f.w)};
    *(uint2*)(dst + i4) = *(uint2*)hh;
}
__device__ __forceinline__ void cvt4_slice(const float* src, __half* dst,
                                           size_t i4, int off) {
    int row = (int)(i4 / Dc);
    int col = (int)(i4 - (size_t)row * Dc);
    float4 f = *(const float4*)(src + i4);
    __half hh[4] = {__float2half_rn(f.x), __float2half_rn(f.y),
                    __float2half_rn(f.z), __float2half_rn(f.w)};
    *(uint2*)(dst + (size_t)row * QKVW + off + col) = *(uint2*)hh;
}

__global__ __launch_bounds__(256)
void cvt_all(const float* __restrict__ wq, const float* __restrict__ wk,
             const float* __restrict__ wv, const float* __restrict__ wo,
             const float* __restrict__ w1, const float* __restrict__ w2,
             const float* __restrict__ x,
             const float* __restrict__ bq, const float* __restrict__ bk,
             const float* __restrict__ bv)
{
    const int bid = blockIdx.x;
    if (bid < CB_B0) {
        const int seg = bid / CB_WQ;           // 0,1,2
        const int lb  = bid - seg * CB_WQ;
        size_t i4 = ((size_t)lb * 256 + threadIdx.x) * 4;
        const float* src = (seg == 0) ? wq : (seg == 1) ? wk : wv;
        cvt4_slice(src, g_wqkv, i4, seg * Dc);
    } else if (bid < CB_B1) {
        size_t i4 = ((size_t)(bid - CB_B0) * 256 + threadIdx.x) * 4;
        cvt4_to(wo, g_woh, i4);
    } else if (bid < CB_B2) {
        size_t i4 = ((size_t)(bid - CB_B1) * 256 + threadIdx.x) * 4;
        cvt4_to(w1, g_w1h, i4);
    } else if (bid < CB_B3) {
        size_t i4 = ((size_t)(bid - CB_B2) * 256 + threadIdx.x) * 4;
        cvt4_to(w2, g_w2h, i4);
    } else if (bid < CB_B4) {
        size_t i4 = ((size_t)(bid - CB_B3) * 256 + threadIdx.x) * 4;
        cvt4_to(x, g_xh, i4);
    } else {
        for (int i = threadIdx.x; i < QKVW; i += 256)
            g_bqkv[i] = (i < Dc) ? bq[i]
                       : (i < 2 * Dc) ? bk[i - Dc] : bv[i - 2 * Dc];
    }
}

// ---------------------------------------------------------------------------
// fp16 tensor GEMM, 1-term: C = A @ W (+ bias for EMIT 2)
// EMIT: 0 => raw f32 partial (split-K via blockIdx.z); 2 => fp16 + bias(+ReLU)
// __launch_bounds__(256, 2): force 2 CTAs/SM residency for latency hiding.
// ---------------------------------------------------------------------------
#define HG_ASZ   (128 * 40)
#define HG_WSZ   (32 * 136)
#define HG_BUF   (HG_ASZ + HG_WSZ)
#define HG_SMEM  (2 * HG_BUF * 2)

template<int RELU, int EMIT>
__global__ __launch_bounds__(256, 2)
void hgemm(const __half* __restrict__ Ah_g,
           const __half* __restrict__ Wh_g,
           const float* __restrict__ bias,
           float* __restrict__ Cf, __half* __restrict__ Ch,
           int Ndim, int Kdim, int Kstride, size_t CfStride)
{
    extern __shared__ __half sh[];
    const int tid  = threadIdx.x;
    const int lane = tid & 31;
    const int wid  = tid >> 5;
    const int wm   = (wid & 1) * 64;
    const int wn   = (wid >> 1) * 32;
    const int bM   = blockIdx.y * 128;
    const int bN   = blockIdx.x * 128;
    const int kz   = blockIdx.z;
    const int kbase = kz * Kdim;

    const int ar = tid >> 1, ac = (tid & 1) * 16;
    const int wr = tid >> 3, wc = (tid & 7) * 16;

    const __half* gAh = Ah_g + (size_t)(bM + ar) * Kstride + kbase + ac;
    const __half* gWh = Wh_g + (size_t)(kbase + wr) * Ndim + bN + wc;
    const size_t WkS = (size_t)32 * Ndim;

    auto stage = [&](int b, int k0) {
        __half* pAh = sh + b * HG_BUF;
        __half* pWh = pAh + HG_ASZ;
        cpasync16(pAh + ar * 40 + ac,     gAh + k0);
        cpasync16(pAh + ar * 40 + ac + 8, gAh + k0 + 8);
        cpasync16(pWh + wr * 136 + wc,     gWh + (size_t)(k0 / 32) * WkS);
        cpasync16(pWh + wr * 136 + wc + 8, gWh + (size_t)(k0 / 32) * WkS + 8);
        cpcommit();
    };

    float acc[4][4][4];
#pragma unroll
    for (int a = 0; a < 4; a++)
#pragma unroll
        for (int b = 0; b < 4; b++)
#pragma unroll
            for (int c = 0; c < 4; c++) acc[a][b][c] = 0.f;

    const int lr    = lane & 15;
    const int lc8   = (lane >> 4) * 8;
    const int brow  = (lane & 7) + ((lane >> 3) & 1) * 8;
    const int bcol8 = (lane >> 4) * 8;

    const int T = Kdim / 32;
    stage(0, 0);

    for (int t = 0; t < T; t++) {
        const int b = t & 1;
        if (t + 1 < T) { stage((t + 1) & 1, (t + 1) * 32); cpwait<1>(); }
        else           { cpwait<0>(); }
        __syncthreads();

        __half* pAh = sh + b * HG_BUF;
        __half* pWh = pAh + HG_ASZ;

#pragma unroll
        for (int ks = 0; ks < 32; ks += 16) {
            uint32_t ah[4][4];
#pragma unroll
            for (int mi = 0; mi < 4; mi++)
                ldsm4(ah[mi], sptr(pAh + (wm + mi * 16 + lr) * 40 + ks + lc8));
#pragma unroll
            for (int p = 0; p < 2; p++) {
                uint32_t bh[4];
                ldsm4t(bh, sptr(pWh + (ks + brow) * 136 + wn + p * 16 + bcol8));
#pragma unroll
                for (int s = 0; s < 2; s++) {
                    const int ni = p * 2 + s;
#pragma unroll
                    for (int mi = 0; mi < 4; mi++)
                        mma16816h(acc[mi][ni], ah[mi], bh[s * 2], bh[s * 2 + 1]);
                }
            }
        }
        __syncthreads();
    }

    const int gr = lane >> 2, gc = (lane & 3) * 2;
    float* Cfz = Cf + (size_t)kz * CfStride;
#pragma unroll
    for (int mi = 0; mi < 4; mi++) {
#pragma unroll
        for (int ni = 0; ni < 4; ni++) {
            int row = bM + wm + mi * 16 + gr;
            int col = bN + wn + ni * 8 + gc;
            if (EMIT == 0) {
                *(float2*)&Cfz[(size_t)row * Ndim + col] =
                    make_float2(acc[mi][ni][0], acc[mi][ni][1]);
                *(float2*)&Cfz[(size_t)(row + 8) * Ndim + col] =
                    make_float2(acc[mi][ni][2], acc[mi][ni][3]);
            } else {
                float b0 = bias[col], b1 = bias[col + 1];
                float v0 = acc[mi][ni][0] + b0, v1 = acc[mi][ni][1] + b1;
                float v2 = acc[mi][ni][2] + b0, v3 = acc[mi][ni][3] + b1;
                if (RELU) {
                    v0 = fmaxf(v0, 0.f); v1 = fmaxf(v1, 0.f);
                    v2 = fmaxf(v2, 0.f); v3 = fmaxf(v3, 0.f);
                }
                uint32_t h0, h1;
                pack2h(v0, v1, h0);
                pack2h(v2, v3, h1);
                *(uint32_t*)&Ch[(size_t)row * Ndim + col]       = h0;
                *(uint32_t*)&Ch[(size_t)(row + 8) * Ndim + col] = h1;
            }
        }
    }
}

// ---------------------------------------------------------------------------
// fp16 flash attention, 1-term, K/V double-buffered. QT=128, KT=64.
// ---------------------------------------------------------------------------
struct AttnSmem4 {
    __half Qh[128][72];
    __half Kh[2][64][72];
    __half Vh[2][64][72];
};

__global__ __launch_bounds__(256, 2)
void attn_mma(const int* __restrict__ mask)
{
    extern __shared__ char sraw[];
    AttnSmem4& sm = *reinterpret_cast<AttnSmem4*>(sraw);

    const int tid = threadIdx.x, lane = tid & 31, wid = tid >> 5;
    const int qb = blockIdx.x, bh = blockIdx.y;
    const int b = bh / Hc, h = bh - b * Hc;
    const int q0 = qb * 128, rb = b * Sc, c0 = h * DKc;

    const int kr = tid >> 2, kcb = (tid & 3) * 16;
    const __half* gK_h = g_qkvh + (size_t)(rb + kr) * QKVW + Dc + c0 + kcb;
    const __half* gV_h = g_qkvh + (size_t)(rb + kr) * QKVW + 2 * Dc + c0 + kcb;

    auto stage_kv = [&](int buf, int k0) {
        const size_t go = (size_t)k0 * QKVW;
        cpasync16(&sm.Kh[buf][kr][kcb],     gK_h + go);
        cpasync16(&sm.Kh[buf][kr][kcb + 8], gK_h + go + 8);
        cpasync16(&sm.Vh[buf][kr][kcb],     gV_h + go);
        cpasync16(&sm.Vh[buf][kr][kcb + 8], gV_h + go + 8);
        cpcommit();
    };

    {
        int r = tid >> 1, cb = (tid & 1) * 32;
        const __half* gq_h = g_qkvh + (size_t)(rb + q0 + r) * QKVW + c0 + cb;
#pragma unroll
        for (int j = 0; j < 4; j++)
            cpasync16(&sm.Qh[r][cb + j * 8], gq_h + j * 8);
        cpcommit();
    }
    stage_kv(0, 0);
    cpwait<0>();
    __syncthreads();

    const int lr = lane & 15, lc8 = (lane >> 4) * 8;
    const int wq0 = wid * 16;
    uint32_t qh[4][4];
#pragma unroll
    for (int kt = 0; kt < 4; kt++)
        ldsm4(qh[kt], sptr(&sm.Qh[wq0 + lr][kt * 16 + lc8]));

    const int g  = lane >> 2, tg = lane & 3;
    const int krow  = (lane & 7) + ((lane >> 4) << 3);
    const int kcol  = ((lane >> 3) & 1) * 8;
    const int brow  = (lane & 7) + ((lane >> 3) & 1) * 8;
    const int bcol8 = (lane >> 4) * 8;

    float oacc[8][4];
#pragma unroll
    for (int i = 0; i < 8; i++)
#pragma unroll
        for (int j = 0; j < 4; j++) oacc[i][j] = 0.f;
    float m0 = -INFINITY, m1 = -INFINITY, l0 = 0.f, l1 = 0.f;

    const int* mr0base = mask + (size_t)(q0 + wq0 + g) * Sc + 2 * tg;
    constexpr int NIT = Sc / 64;   // 32 tiles

    for (int it = 0; it < NIT; it++) {
        const int buf = it & 1;
        if (it + 1 < NIT) { stage_kv((it + 1) & 1, (it + 1) * 64); cpwait<1>(); }
        else              { cpwait<0>(); }
        __syncthreads();
        const int k0 = it * 64;

        // ---- S = Q K^T ----
        float s[8][4];
#pragma unroll
        for (int i = 0; i < 8; i++)
#pragma unroll
            for (int j = 0; j < 4; j++) s[i][j] = 0.f;

#pragma unroll
        for (int kt = 0; kt < 4; kt++) {
#pragma unroll
            for (int p = 0; p < 4; p++) {
                uint32_t kbh[4];
                ldsm4(kbh, sptr(&sm.Kh[buf][p * 16 + krow][kt * 16 + kcol]));
                mma16816h(s[2 * p],     qh[kt], kbh[0], kbh[1]);
                mma16816h(s[2 * p + 1], qh[kt], kbh[2], kbh[3]);
            }
        }

        // ---- scale + mask ----
        const int* mr0 = mr0base + k0;
        const int* mr1 = mr0 + 8 * Sc;
#pragma unroll
        for (int ni = 0; ni < 8; ni++) {
            int2 ma = *(const int2*)(mr0 + 8 * ni);
            int2 mb = *(const int2*)(mr1 + 8 * ni);
            s[ni][0] = ma.x ? s[ni][0] * 0.125f : -1e9f;
            s[ni][1] = ma.y ? s[ni][1] * 0.125f : -1e9f;
            s[ni][2] = mb.x ? s[ni][2] * 0.125f : -1e9f;
            s[ni][3] = mb.y ? s[ni][3] * 0.125f : -1e9f;
        }

        // ---- online softmax ----
        float mx0 = -INFINITY, mx1 = -INFINITY;
#pragma unroll
        for (int ni = 0; ni < 8; ni++) {
            mx0 = fmaxf(mx0, fmaxf(s[ni][0], s[ni][1]));
            mx1 = fmaxf(mx1, fmaxf(s[ni][2], s[ni][3]));
        }
        mx0 = fmaxf(mx0, __shfl_xor_sync(0xffffffffu, mx0, 1));
        mx0 = fmaxf(mx0, __shfl_xor_sync(0xffffffffu, mx0, 2));
        mx1 = fmaxf(mx1, __shfl_xor_sync(0xffffffffu, mx1, 1));
        mx1 = fmaxf(mx1, __shfl_xor_sync(0xffffffffu, mx1, 2));

        float mn0 = fmaxf(m0, mx0), mn1 = fmaxf(m1, mx1);
        float a0 = __expf(m0 - mn0), a1 = __expf(m1 - mn1);
        m0 = mn0; m1 = mn1;

        float sum0 = 0.f, sum1 = 0.f;
#pragma unroll
        for (int ni = 0; ni < 8; ni++) {
            s[ni][0] = __expf(s[ni][0] - mn0); sum0 += s[ni][0];
            s[ni][1] = __expf(s[ni][1] - mn0); sum0 += s[ni][1];
            s[ni][2] = __expf(s[ni][2] - mn1); sum1 += s[ni][2];
            s[ni][3] = __expf(s[ni][3] - mn1); sum1 += s[ni][3];
        }
        sum0 += __shfl_xor_sync(0xffffffffu, sum0, 1);
        sum0 += __shfl_xor_sync(0xffffffffu, sum0, 2);
        sum1 += __shfl_xor_sync(0xffffffffu, sum1, 1);
        sum1 += __shfl_xor_sync(0xffffffffu, sum1, 2);
        l0 = l0 * a0 + sum0;
        l1 = l1 * a1 + sum1;

#pragma unroll
        for (int ni = 0; ni < 8; ni++) {
            oacc[ni][0] *= a0; oacc[ni][1] *= a0;
            oacc[ni][2] *= a1; oacc[ni][3] *= a1;
        }

        // ---- O += P @ V ----
#pragma unroll
        for (int kt = 0; kt < 4; kt++) {
            uint32_t pah[4];
            pack2h(s[2 * kt][0],     s[2 * kt][1],     pah[0]);
            pack2h(s[2 * kt][2],     s[2 * kt][3],     pah[1]);
            pack2h(s[2 * kt + 1][0], s[2 * kt + 1][1], pah[2]);
            pack2h(s[2 * kt + 1][2], s[2 * kt + 1][3], pah[3]);
#pragma unroll
            for (int p = 0; p < 4; p++) {
                uint32_t vbh[4];
                ldsm4t(vbh, sptr(&sm.Vh[buf][kt * 16 + brow][p * 16 + bcol8]));
                mma16816h(oacc[2 * p],     pah, vbh[0], vbh[1]);
                mma16816h(oacc[2 * p + 1], pah, vbh[2], vbh[3]);
            }
        }
        __syncthreads();
    }

    // epilogue: emit ctx as fp16
    float i0 = 1.f / l0, i1 = 1.f / l1;
    const int r0 = rb + q0 + wq0 + g;
#pragma unroll
    for (int ni = 0; ni < 8; ni++) {
        int col = c0 + 8 * ni + 2 * tg;
        uint32_t h0, h1;
        pack2h(oacc[ni][0] * i0, oacc[ni][1] * i0, h0);
        pack2h(oacc[ni][2] * i1, oacc[ni][3] * i1, h1);
        *(uint32_t*)&g_ctxh[(size_t)r0 * Dc + col]       = h0;
        *(uint32_t*)&g_ctxh[(size_t)(r0 + 8) * Dc + col] = h1;
    }
}

// ---------------------------------------------------------------------------
// add + layernorm over (x + yA + yB + bias); EMIT_H: also emit fp16
// ---------------------------------------------------------------------------
template<int EMIT_H>
__global__ __launch_bounds__(256)
void add_ln_kernel(const float* __restrict__ x,
                   const float* __restrict__ yA, const float* __restrict__ yB,
                   const float* __restrict__ bias,
                   const float* __restrict__ alpha, const float* __restrict__ beta,
                   float* __restrict__ out, __half* __restrict__ oh)
{
    const int row = blockIdx.x;
    const int tid = threadIdx.x;
    const float* xr = x  + (size_t)row * Dc;
    const float* ya = yA + (size_t)row * Dc;
    const float* yb = yB + (size_t)row * Dc;

    __shared__ float red[8];
    __shared__ float sm_mean, sm_scale;

    float v[3];
    float s = 0.f;
#pragma unroll
    for (int t = 0; t < 3; t++) {
        int c = tid + 256 * t;
        v[t] = xr[c] + ya[c] + yb[c] + bias[c];
        s += v[t];
    }
#pragma unroll
    for (int o = 16; o > 0; o >>= 1) s += __shfl_xor_sync(0xFFFFFFFFu, s, o);
    if ((tid & 31) == 0) red[tid >> 5] = s;
    __syncthreads();
    if (tid == 0) {
        float tot = 0.f;
#pragma unroll
        for (int w = 0; w < 8; w++) tot += red[w];
        sm_mean = tot * (1.0f / (float)Dc);
    }
    __syncthreads();
    const float mean = sm_mean;

    float sq = 0.f;
#pragma unroll
    for (int t = 0; t < 3; t++) {
        float d = v[t] - mean;
        sq += d * d;
    }
#pragma unroll
    for (int o = 16; o > 0; o >>= 1) sq += __shfl_xor_sync(0xFFFFFFFFu, sq, o);
    if ((tid & 31) == 0) red[tid >> 5] = sq;
    __syncthreads();
    if (tid == 0) {
        float tot = 0.f;
#pragma unroll
        for (int w = 0; w < 8; w++) tot += red[w];
        float var = tot * (1.0f / (float)(Dc - 1));
        sm_scale = 1.0f / (sqrtf(var) + 1e-6f);
    }
    __syncthreads();

    const float sc = sm_scale * alpha[0];
    const float bt = beta[0];
#pragma unroll
    for (int t = 0; t < 3; t++) {
        float o = (v[t] - mean) * sc + bt;
        out[(size_t)row * Dc + tid + 256 * t] = o;
        if (EMIT_H)
            oh[(size_t)row * Dc + tid + 256 * t] = __float2half_rn(o);
    }
}

// ---------------------------------------------------------------------------
extern "C" void kernel_launch(void* const* d_in, const int* in_sizes, int n_in,
                              void* d_out, int out_size)
{
    const float* x      = (const float*)d_in[0];
    const float* wq     = (const float*)d_in[1];
    const float* bq     = (const float*)d_in[2];
    const float* wk     = (const float*)d_in[3];
    const float* bk     = (const float*)d_in[4];
    const float* wv     = (const float*)d_in[5];
    const float* bv     = (const float*)d_in[6];
    const float* wo     = (const float*)d_in[7];
    const float* bo     = (const float*)d_in[8];
    const float* w1     = (const float*)d_in[9];
    const float* b1     = (const float*)d_in[10];
    const float* w2     = (const float*)d_in[11];
    const float* b2     = (const float*)d_in[12];
    const float* alpha1 = (const float*)d_in[13];
    const float* beta1  = (const float*)d_in[14];
    const float* alpha2 = (const float*)d_in[15];
    const float* beta2  = (const float*)d_in[16];
    const int*   mask   = (const int*)d_in[17];

    float *tmp, *x1;
    cudaGetSymbolAddress((void**)&tmp, g_tmp);
    cudaGetSymbolAddress((void**)&x1,  g_x1);

    __half *xh, *qkvh, *ctxh, *x1h, *ff1h;
    cudaGetSymbolAddress((void**)&xh,   g_xh);
    cudaGetSymbolAddress((void**)&qkvh, g_qkvh);
    cudaGetSymbolAddress((void**)&ctxh, g_ctxh);
    cudaGetSymbolAddress((void**)&x1h,  g_x1h);
    cudaGetSymbolAddress((void**)&ff1h, g_ff1h);

    __half *wqkv, *woh, *w1h, *w2h;
    float  *bqkv;
    cudaGetSymbolAddress((void**)&wqkv, g_wqkv);
    cudaGetSymbolAddress((void**)&bqkv, g_bqkv);
    cudaGetSymbolAddress((void**)&woh,  g_woh);
    cudaGetSymbolAddress((void**)&w1h,  g_w1h);
    cudaGetSymbolAddress((void**)&w2h,  g_w2h);

    const size_t CS = (size_t)Mc * Dc;   // split-K output slice stride
    float* tmpA = tmp;
    float* tmpB = tmp + CS;

    int attn_smem = (int)sizeof(AttnSmem4);
    cudaFuncSetAttribute(attn_mma, cudaFuncAttributeMaxDynamicSharedMemorySize, attn_smem);
    cudaFuncSetAttribute(hgemm<0, 0>, cudaFuncAttributeMaxDynamicSharedMemorySize, HG_SMEM);
    cudaFuncSetAttribute(hgemm<0, 2>, cudaFuncAttributeMaxDynamicSharedMemorySize, HG_SMEM);
    cudaFuncSetAttribute(hgemm<1, 2>, cudaFuncAttributeMaxDynamicSharedMemorySize, HG_SMEM);

    dim3 blk(256);

    // 1. all conversions in one launch
    cvt_all<<<CB_TOTAL, blk>>>(wq, wk, wv, wo, w1, w2, x, bq, bk, bv);

    // 2. fused QKV projection: one uniform GEMM, N=2304, 576 CTAs
    hgemm<0, 2><<<dim3(QKVW / 128, Mc / 128, 1), blk, HG_SMEM>>>(
        xh, wqkv, bqkv, nullptr, qkvh, QKVW, Dc, Dc, 0);

    // 3. flash attention (double-buffered K/V)
    attn_mma<<<dim3(Sc / 128, Bc * Hc), blk, attn_smem>>>(mask);

    // 4. O-projection split-K x2 (raw partials), LN1 folds bias bo
    hgemm<0, 0><<<dim3(Dc / 128, Mc / 128, 2), blk, HG_SMEM>>>(
        ctxh, woh, nullptr, tmpA, nullptr, Dc, Dc / 2, Dc, CS);
    add_ln_kernel<1><<<Mc, blk>>>(x, tmpA, tmpB, bo, alpha1, beta1, x1, x1h);

    // 5. FFN
    hgemm<1, 2><<<dim3(DFFc / 128, Mc / 128, 1), blk, HG_SMEM>>>(
        x1h, w1h, b1, nullptr, ff1h, DFFc, Dc, Dc, 0);
    hgemm<0, 0><<<dim3(Dc / 128, Mc / 128, 2), blk, HG_SMEM>>>(
        ff1h, w2h, nullptr, tmpA, nullptr, Dc, DFFc / 2, DFFc, CS);
    add_ln_kernel<0><<<Mc, blk>>>(x1, tmpA, tmpB, b2, alpha2, beta2,
                                  (float*)d_out, nullptr);
}

// round 17
// speedup vs baseline: 1.0424x; 1.0424x over previous
#include <cuda_runtime.h>
#include <cuda_fp16.h>
#include <stdint.h>
#include <math.h>

// Problem constants
static constexpr int Bc   = 2;
static constexpr int Sc   = 2048;
static constexpr int Dc   = 768;
static constexpr int Hc   = 12;
static constexpr int DKc  = 64;
static constexpr int DFFc = 3072;
static constexpr int Mc   = Bc * Sc;     // 4096 rows
static constexpr int QKVW = 3 * Dc;      // 2304 fused qkv width

// f32 scratch: two split-K partial slices, contiguous by construction
__device__ float g_tmp[2 * Mc * Dc];
__device__ float g_x1 [Mc * Dc];

// fp16 activations
__device__ __half g_xh  [Mc * Dc];
__device__ __half g_qkvh[Mc * QKVW];     // fused q|k|v, row stride 2304
__device__ __half g_ctxh[Mc * Dc];
__device__ __half g_x1h [Mc * Dc];
__device__ __half g_ff1h[Mc * DFFc];

// fp16 weights
__device__ __half g_wqkv[Dc * QKVW];     // wq|wk|wv fused, row stride 2304
__device__ float  g_bqkv[QKVW];          // bq|bk|bv fused
__device__ __half g_woh[Dc * Dc];
__device__ __half g_w1h[Dc * DFFc];
__device__ __half g_w2h[DFFc * Dc];

// ---------------------------------------------------------------------------
// helpers
// ---------------------------------------------------------------------------
__device__ __forceinline__ uint32_t sptr(const void* p) {
    return (uint32_t)__cvta_generic_to_shared(p);
}
__device__ __forceinline__ void ldsm4(uint32_t r[4], uint32_t addr) {
    asm volatile("ldmatrix.sync.aligned.m8n8.x4.shared.b16 {%0,%1,%2,%3},[%4];"
                 : "=r"(r[0]), "=r"(r[1]), "=r"(r[2]), "=r"(r[3]) : "r"(addr));
}
__device__ __forceinline__ void ldsm4t(uint32_t r[4], uint32_t addr) {
    asm volatile("ldmatrix.sync.aligned.m8n8.x4.trans.shared.b16 {%0,%1,%2,%3},[%4];"
                 : "=r"(r[0]), "=r"(r[1]), "=r"(r[2]), "=r"(r[3]) : "r"(addr));
}
__device__ __forceinline__ void mma16816h(float c[4], const uint32_t a[4],
                                          uint32_t b0, uint32_t b1) {
    asm volatile(
        "mma.sync.aligned.m16n8k16.row.col.f32.f16.f16.f32 "
        "{%0,%1,%2,%3},{%4,%5,%6,%7},{%8,%9},{%0,%1,%2,%3};"
        : "+f"(c[0]), "+f"(c[1]), "+f"(c[2]), "+f"(c[3])
        : "r"(a[0]), "r"(a[1]), "r"(a[2]), "r"(a[3]), "r"(b0), "r"(b1));
}
__device__ __forceinline__ void pack2h(float a, float b, uint32_t& h) {
    __half2 H; H.x = __float2half_rn(a); H.y = __float2half_rn(b);
    h = *(uint32_t*)&H;
}
__device__ __forceinline__ void cpasync16(const void* smem, const void* gmem) {
    asm volatile("cp.async.cg.shared.global [%0],[%1],16;"
                 :: "r"(sptr(smem)), "l"(gmem));
}
__device__ __forceinline__ void cpcommit() { asm volatile("cp.async.commit_group;"); }
template<int N>
__device__ __forceinline__ void cpwait() {
    asm volatile("cp.async.wait_group %0;" :: "n"(N));
}

// ---------------------------------------------------------------------------
// ONE fused conversion kernel: all weights, x, and bias concat.
// ---------------------------------------------------------------------------
static constexpr int CB_WQ   = Dc * Dc / 1024;            // 576
static constexpr int CB_WO   = CB_WQ;
static constexpr int CB_W1   = Dc * DFFc / 1024;          // 2304
static constexpr int CB_W2   = DFFc * Dc / 1024;          // 2304
static constexpr int CB_X    = Mc * Dc / 1024;            // 3072
static constexpr int CB_B0   = CB_WQ * 3;                 // 1728
static constexpr int CB_B1   = CB_B0 + CB_WO;             // 2304
static constexpr int CB_B2   = CB_B1 + CB_W1;             // 4608
static constexpr int CB_B3   = CB_B2 + CB_W2;             // 6912
static constexpr int CB_B4   = CB_B3 + CB_X;              // 9984
static constexpr int CB_TOTAL = CB_B4 + 1;                // + bias block

__device__ __forceinline__ void cvt4_to(const float* src, __half* dst, size_t i4) {
    float4 f = *(const float4*)(src + i4);
    __half hh[4] = {__float2half_rn(f.x), __float2half_rn(f.y),
                    __float2half_rn(f.z), __float2half_rn(f.w)};
    *(uint2*)(dst + i4) = *(uint2*)hh;
}
__device__ __forceinline__ void cvt4_slice(const float* src, __half* dst,
                                           size_t i4, int off) {
    int row = (int)(i4 / Dc);
    int col = (int)(i4 - (size_t)row * Dc);
    float4 f = *(const float4*)(src + i4);
    __half hh[4] = {__float2half_rn(f.x), __float2half_rn(f.y),
                    __float2half_rn(f.z), __float2half_rn(f.w)};
    *(uint2*)(dst + (size_t)row * QKVW + off + col) = *(uint2*)hh;
}

__global__ __launch_bounds__(256)
void cvt_all(const float* __restrict__ wq, const float* __restrict__ wk,
             const float* __restrict__ wv, const float* __restrict__ wo,
             const float* __restrict__ w1, const float* __restrict__ w2,
             const float* __restrict__ x,
             const float* __restrict__ bq, const float* __restrict__ bk,
             const float* __restrict__ bv)
{
    const int bid = blockIdx.x;
    if (bid < CB_B0) {
        const int seg = bid / CB_WQ;           // 0,1,2
        const int lb  = bid - seg * CB_WQ;
        size_t i4 = ((size_t)lb * 256 + threadIdx.x) * 4;
        const float* src = (seg == 0) ? wq : (seg == 1) ? wk : wv;
        cvt4_slice(src, g_wqkv, i4, seg * Dc);
    } else if (bid < CB_B1) {
        size_t i4 = ((size_t)(bid - CB_B0) * 256 + threadIdx.x) * 4;
        cvt4_to(wo, g_woh, i4);
    } else if (bid < CB_B2) {
        size_t i4 = ((size_t)(bid - CB_B1) * 256 + threadIdx.x) * 4;
        cvt4_to(w1, g_w1h, i4);
    } else if (bid < CB_B3) {
        size_t i4 = ((size_t)(bid - CB_B2) * 256 + threadIdx.x) * 4;
        cvt4_to(w2, g_w2h, i4);
    } else if (bid < CB_B4) {
        size_t i4 = ((size_t)(bid - CB_B3) * 256 + threadIdx.x) * 4;
        cvt4_to(x, g_xh, i4);
    } else {
        for (int i = threadIdx.x; i < QKVW; i += 256)
            g_bqkv[i] = (i < Dc) ? bq[i]
                       : (i < 2 * Dc) ? bk[i - Dc] : bv[i - 2 * Dc];
    }
}

// ---------------------------------------------------------------------------
// fp16 tensor GEMM, 1-term: C = A @ W (+ bias for EMIT 2)
// EMIT: 0 => raw f32 partial (split-K via blockIdx.z); 2 => fp16 + bias(+ReLU)
// 3-stage cp.async ring; ONE __syncthreads per K-iteration:
//   cpwait(t done) -> barrier -> stage(t+2) -> compute(t)
// The barrier both publishes tile t and fences compute(t-1) against the
// stage(t+2) overwrite of buffer (t-1)%3.
// ---------------------------------------------------------------------------
#define HG_ASZ   (128 * 40)
#define HG_WSZ   (32 * 136)
#define HG_BUF   (HG_ASZ + HG_WSZ)
#define HG_SMEM  (3 * HG_BUF * 2)

template<int RELU, int EMIT>
__global__ __launch_bounds__(256, 2)
void hgemm(const __half* __restrict__ Ah_g,
           const __half* __restrict__ Wh_g,
           const float* __restrict__ bias,
           float* __restrict__ Cf, __half* __restrict__ Ch,
           int Ndim, int Kdim, int Kstride, size_t CfStride)
{
    extern __shared__ __half sh[];
    const int tid  = threadIdx.x;
    const int lane = tid & 31;
    const int wid  = tid >> 5;
    const int wm   = (wid & 1) * 64;
    const int wn   = (wid >> 1) * 32;
    const int bM   = blockIdx.y * 128;
    const int bN   = blockIdx.x * 128;
    const int kz   = blockIdx.z;
    const int kbase = kz * Kdim;

    const int ar = tid >> 1, ac = (tid & 1) * 16;
    const int wr = tid >> 3, wc = (tid & 7) * 16;

    const __half* gAh = Ah_g + (size_t)(bM + ar) * Kstride + kbase + ac;
    const __half* gWh = Wh_g + (size_t)(kbase + wr) * Ndim + bN + wc;
    const size_t WkS = (size_t)32 * Ndim;

    auto stage = [&](int b, int k0) {
        __half* pAh = sh + b * HG_BUF;
        __half* pWh = pAh + HG_ASZ;
        cpasync16(pAh + ar * 40 + ac,     gAh + k0);
        cpasync16(pAh + ar * 40 + ac + 8, gAh + k0 + 8);
        cpasync16(pWh + wr * 136 + wc,     gWh + (size_t)(k0 / 32) * WkS);
        cpasync16(pWh + wr * 136 + wc + 8, gWh + (size_t)(k0 / 32) * WkS + 8);
        cpcommit();
    };

    float acc[4][4][4];
#pragma unroll
    for (int a = 0; a < 4; a++)
#pragma unroll
        for (int b = 0; b < 4; b++)
#pragma unroll
            for (int c = 0; c < 4; c++) acc[a][b][c] = 0.f;

    const int lr    = lane & 15;
    const int lc8   = (lane >> 4) * 8;
    const int brow  = (lane & 7) + ((lane >> 3) & 1) * 8;
    const int bcol8 = (lane >> 4) * 8;

    const int T = Kdim / 32;
    stage(0, 0);
    if (T > 1) stage(1, 32);

    for (int t = 0; t < T; t++) {
        if (t + 1 < T) cpwait<1>();
        else           cpwait<0>();
        __syncthreads();
        if (t + 2 < T) stage((t + 2) % 3, (t + 2) * 32);

        const int b = t % 3;
        __half* pAh = sh + b * HG_BUF;
        __half* pWh = pAh + HG_ASZ;

#pragma unroll
        for (int ks = 0; ks < 32; ks += 16) {
            uint32_t ah[4][4];
#pragma unroll
            for (int mi = 0; mi < 4; mi++)
                ldsm4(ah[mi], sptr(pAh + (wm + mi * 16 + lr) * 40 + ks + lc8));
#pragma unroll
            for (int p = 0; p < 2; p++) {
                uint32_t bh[4];
                ldsm4t(bh, sptr(pWh + (ks + brow) * 136 + wn + p * 16 + bcol8));
#pragma unroll
                for (int s = 0; s < 2; s++) {
                    const int ni = p * 2 + s;
#pragma unroll
                    for (int mi = 0; mi < 4; mi++)
                        mma16816h(acc[mi][ni], ah[mi], bh[s * 2], bh[s * 2 + 1]);
                }
            }
        }
    }

    const int gr = lane >> 2, gc = (lane & 3) * 2;
    float* Cfz = Cf + (size_t)kz * CfStride;
#pragma unroll
    for (int mi = 0; mi < 4; mi++) {
#pragma unroll
        for (int ni = 0; ni < 4; ni++) {
            int row = bM + wm + mi * 16 + gr;
            int col = bN + wn + ni * 8 + gc;
            if (EMIT == 0) {
                *(float2*)&Cfz[(size_t)row * Ndim + col] =
                    make_float2(acc[mi][ni][0], acc[mi][ni][1]);
                *(float2*)&Cfz[(size_t)(row + 8) * Ndim + col] =
                    make_float2(acc[mi][ni][2], acc[mi][ni][3]);
            } else {
                float b0 = bias[col], b1 = bias[col + 1];
                float v0 = acc[mi][ni][0] + b0, v1 = acc[mi][ni][1] + b1;
                float v2 = acc[mi][ni][2] + b0, v3 = acc[mi][ni][3] + b1;
                if (RELU) {
                    v0 = fmaxf(v0, 0.f); v1 = fmaxf(v1, 0.f);
                    v2 = fmaxf(v2, 0.f); v3 = fmaxf(v3, 0.f);
                }
                uint32_t h0, h1;
                pack2h(v0, v1, h0);
                pack2h(v2, v3, h1);
                *(uint32_t*)&Ch[(size_t)row * Ndim + col]       = h0;
                *(uint32_t*)&Ch[(size_t)(row + 8) * Ndim + col] = h1;
            }
        }
    }
}

// ---------------------------------------------------------------------------
// fp16 flash attention, 1-term, 3-stage K/V ring, one barrier per tile.
// QT=128, KT=64.
// ---------------------------------------------------------------------------
struct AttnSmem5 {
    __half Qh[128][72];
    __half Kh[3][64][72];
    __half Vh[3][64][72];
};

__global__ __launch_bounds__(256, 2)
void attn_mma(const int* __restrict__ mask)
{
    extern __shared__ char sraw[];
    AttnSmem5& sm = *reinterpret_cast<AttnSmem5*>(sraw);

    const int tid = threadIdx.x, lane = tid & 31, wid = tid >> 5;
    const int qb = blockIdx.x, bh = blockIdx.y;
    const int b = bh / Hc, h = bh - b * Hc;
    const int q0 = qb * 128, rb = b * Sc, c0 = h * DKc;

    const int kr = tid >> 2, kcb = (tid & 3) * 16;
    const __half* gK_h = g_qkvh + (size_t)(rb + kr) * QKVW + Dc + c0 + kcb;
    const __half* gV_h = g_qkvh + (size_t)(rb + kr) * QKVW + 2 * Dc + c0 + kcb;

    auto stage_kv = [&](int buf, int k0) {
        const size_t go = (size_t)k0 * QKVW;
        cpasync16(&sm.Kh[buf][kr][kcb],     gK_h + go);
        cpasync16(&sm.Kh[buf][kr][kcb + 8], gK_h + go + 8);
        cpasync16(&sm.Vh[buf][kr][kcb],     gV_h + go);
        cpasync16(&sm.Vh[buf][kr][kcb + 8], gV_h + go + 8);
        cpcommit();
    };

    // group 1: Q + K/V tile 0; group 2: K/V tile 1
    {
        int r = tid >> 1, cb = (tid & 1) * 32;
        const __half* gq_h = g_qkvh + (size_t)(rb + q0 + r) * QKVW + c0 + cb;
#pragma unroll
        for (int j = 0; j < 4; j++)
            cpasync16(&sm.Qh[r][cb + j * 8], gq_h + j * 8);
    }
    stage_kv(0, 0);          // commits Q + tile0 together
    stage_kv(1, 64);
    cpwait<1>();             // Q + tile0 ready
    __syncthreads();

    const int lr = lane & 15, lc8 = (lane >> 4) * 8;
    const int wq0 = wid * 16;
    uint32_t qh[4][4];
#pragma unroll
    for (int kt = 0; kt < 4; kt++)
        ldsm4(qh[kt], sptr(&sm.Qh[wq0 + lr][kt * 16 + lc8]));

    const int g  = lane >> 2, tg = lane & 3;
    const int krow  = (lane & 7) + ((lane >> 4) << 3);
    const int kcol  = ((lane >> 3) & 1) * 8;
    const int brow  = (lane & 7) + ((lane >> 3) & 1) * 8;
    const int bcol8 = (lane >> 4) * 8;

    float oacc[8][4];
#pragma unroll
    for (int i = 0; i < 8; i++)
#pragma unroll
        for (int j = 0; j < 4; j++) oacc[i][j] = 0.f;
    float m0 = -INFINITY, m1 = -INFINITY, l0 = 0.f, l1 = 0.f;

    const int* mr0base = mask + (size_t)(q0 + wq0 + g) * Sc + 2 * tg;
    constexpr int NIT = Sc / 64;   // 32 tiles

    for (int it = 0; it < NIT; it++) {
        if (it + 1 < NIT) cpwait<1>();
        else              cpwait<0>();
        __syncthreads();
        if (it + 2 < NIT) stage_kv((it + 2) % 3, (it + 2) * 64);

        const int buf = it % 3;
        const int k0 = it * 64;

        // ---- S = Q K^T ----
        float s[8][4];
#pragma unroll
        for (int i = 0; i < 8; i++)
#pragma unroll
            for (int j = 0; j < 4; j++) s[i][j] = 0.f;

#pragma unroll
        for (int kt = 0; kt < 4; kt++) {
#pragma unroll
            for (int p = 0; p < 4; p++) {
                uint32_t kbh[4];
                ldsm4(kbh, sptr(&sm.Kh[buf][p * 16 + krow][kt * 16 + kcol]));
                mma16816h(s[2 * p],     qh[kt], kbh[0], kbh[1]);
                mma16816h(s[2 * p + 1], qh[kt], kbh[2], kbh[3]);
            }
        }

        // ---- scale + mask ----
        const int* mr0 = mr0base + k0;
        const int* mr1 = mr0 + 8 * Sc;
#pragma unroll
        for (int ni = 0; ni < 8; ni++) {
            int2 ma = *(const int2*)(mr0 + 8 * ni);
            int2 mb = *(const int2*)(mr1 + 8 * ni);
            s[ni][0] = ma.x ? s[ni][0] * 0.125f : -1e9f;
            s[ni][1] = ma.y ? s[ni][1] * 0.125f : -1e9f;
            s[ni][2] = mb.x ? s[ni][2] * 0.125f : -1e9f;
            s[ni][3] = mb.y ? s[ni][3] * 0.125f : -1e9f;
        }

        // ---- online softmax ----
        float mx0 = -INFINITY, mx1 = -INFINITY;
#pragma unroll
        for (int ni = 0; ni < 8; ni++) {
            mx0 = fmaxf(mx0, fmaxf(s[ni][0], s[ni][1]));
            mx1 = fmaxf(mx1, fmaxf(s[ni][2], s[ni][3]));
        }
        mx0 = fmaxf(mx0, __shfl_xor_sync(0xffffffffu, mx0, 1));
        mx0 = fmaxf(mx0, __shfl_xor_sync(0xffffffffu, mx0, 2));
        mx1 = fmaxf(mx1, __shfl_xor_sync(0xffffffffu, mx1, 1));
        mx1 = fmaxf(mx1, __shfl_xor_sync(0xffffffffu, mx1, 2));

        float mn0 = fmaxf(m0, mx0), mn1 = fmaxf(m1, mx1);
        float a0 = __expf(m0 - mn0), a1 = __expf(m1 - mn1);
        m0 = mn0; m1 = mn1;

        float sum0 = 0.f, sum1 = 0.f;
#pragma unroll
        for (int ni = 0; ni < 8; ni++) {
            s[ni][0] = __expf(s[ni][0] - mn0); sum0 += s[ni][0];
            s[ni][1] = __expf(s[ni][1] - mn0); sum0 += s[ni][1];
            s[ni][2] = __expf(s[ni][2] - mn1); sum1 += s[ni][2];
            s[ni][3] = __expf(s[ni][3] - mn1); sum1 += s[ni][3];
        }
        sum0 += __shfl_xor_sync(0xffffffffu, sum0, 1);
        sum0 += __shfl_xor_sync(0xffffffffu, sum0, 2);
        sum1 += __shfl_xor_sync(0xffffffffu, sum1, 1);
        sum1 += __shfl_xor_sync(0xffffffffu, sum1, 2);
        l0 = l0 * a0 + sum0;
        l1 = l1 * a1 + sum1;

#pragma unroll
        for (int ni = 0; ni < 8; ni++) {
            oacc[ni][0] *= a0; oacc[ni][1] *= a0;
            oacc[ni][2] *= a1; oacc[ni][3] *= a1;
        }

        // ---- O += P @ V ----
#pragma unroll
        for (int kt = 0; kt < 4; kt++) {
            uint32_t pah[4];
            pack2h(s[2 * kt][0],     s[2 * kt][1],     pah[0]);
            pack2h(s[2 * kt][2],     s[2 * kt][3],     pah[1]);
            pack2h(s[2 * kt + 1][0], s[2 * kt + 1][1], pah[2]);
            pack2h(s[2 * kt + 1][2], s[2 * kt + 1][3], pah[3]);
#pragma unroll
            for (int p = 0; p < 4; p++) {
                uint32_t vbh[4];
                ldsm4t(vbh, sptr(&sm.Vh[buf][kt * 16 + brow][p * 16 + bcol8]));
                mma16816h(oacc[2 * p],     pah, vbh[0], vbh[1]);
                mma16816h(oacc[2 * p + 1], pah, vbh[2], vbh[3]);
            }
        }
    }

    // epilogue: emit ctx as fp16
    float i0 = 1.f / l0, i1 = 1.f / l1;
    const int r0 = rb + q0 + wq0 + g;
#pragma unroll
    for (int ni = 0; ni < 8; ni++) {
        int col = c0 + 8 * ni + 2 * tg;
        uint32_t h0, h1;
        pack2h(oacc[ni][0] * i0, oacc[ni][1] * i0, h0);
        pack2h(oacc[ni][2] * i1, oacc[ni][3] * i1, h1);
        *(uint32_t*)&g_ctxh[(size_t)r0 * Dc + col]       = h0;
        *(uint32_t*)&g_ctxh[(size_t)(r0 + 8) * Dc + col] = h1;
    }
}

// ---------------------------------------------------------------------------
// add + layernorm over (x + yA + yB + bias); EMIT_H: also emit fp16
// ---------------------------------------------------------------------------
template<int EMIT_H>
__global__ __launch_bounds__(256)
void add_ln_kernel(const float* __restrict__ x,
                   const float* __restrict__ yA, const float* __restrict__ yB,
                   const float* __restrict__ bias,
                   const float* __restrict__ alpha, const float* __restrict__ beta,
                   float* __restrict__ out, __half* __restrict__ oh)
{
    const int row = blockIdx.x;
    const int tid = threadIdx.x;
    const float* xr = x  + (size_t)row * Dc;
    const float* ya = yA + (size_t)row * Dc;
    const float* yb = yB + (size_t)row * Dc;

    __shared__ float red[8];
    __shared__ float sm_mean, sm_scale;

    float v[3];
    float s = 0.f;
#pragma unroll
    for (int t = 0; t < 3; t++) {
        int c = tid + 256 * t;
        v[t] = xr[c] + ya[c] + yb[c] + bias[c];
        s += v[t];
    }
#pragma unroll
    for (int o = 16; o > 0; o >>= 1) s += __shfl_xor_sync(0xFFFFFFFFu, s, o);
    if ((tid & 31) == 0) red[tid >> 5] = s;
    __syncthreads();
    if (tid == 0) {
        float tot = 0.f;
#pragma unroll
        for (int w = 0; w < 8; w++) tot += red[w];
        sm_mean = tot * (1.0f / (float)Dc);
    }
    __syncthreads();
    const float mean = sm_mean;

    float sq = 0.f;
#pragma unroll
    for (int t = 0; t < 3; t++) {
        float d = v[t] - mean;
        sq += d * d;
    }
#pragma unroll
    for (int o = 16; o > 0; o >>= 1) sq += __shfl_xor_sync(0xFFFFFFFFu, sq, o);
    if ((tid & 31) == 0) red[tid >> 5] = sq;
    __syncthreads();
    if (tid == 0) {
        float tot = 0.f;
#pragma unroll
        for (int w = 0; w < 8; w++) tot += red[w];
        float var = tot * (1.0f / (float)(Dc - 1));
        sm_scale = 1.0f / (sqrtf(var) + 1e-6f);
    }
    __syncthreads();

    const float sc = sm_scale * alpha[0];
    const float bt = beta[0];
#pragma unroll
    for (int t = 0; t < 3; t++) {
        float o = (v[t] - mean) * sc + bt;
        out[(size_t)row * Dc + tid + 256 * t] = o;
        if (EMIT_H)
            oh[(size_t)row * Dc + tid + 256 * t] = __float2half_rn(o);
    }
}

// ---------------------------------------------------------------------------
extern "C" void kernel_launch(void* const* d_in, const int* in_sizes, int n_in,
                              void* d_out, int out_size)
{
    const float* x      = (const float*)d_in[0];
    const float* wq     = (const float*)d_in[1];
    const float* bq     = (const float*)d_in[2];
    const float* wk     = (const float*)d_in[3];
    const float* bk     = (const float*)d_in[4];
    const float* wv     = (const float*)d_in[5];
    const float* bv     = (const float*)d_in[6];
    const float* wo     = (const float*)d_in[7];
    const float* bo     = (const float*)d_in[8];
    const float* w1     = (const float*)d_in[9];
    const float* b1     = (const float*)d_in[10];
    const float* w2     = (const float*)d_in[11];
    const float* b2     = (const float*)d_in[12];
    const float* alpha1 = (const float*)d_in[13];
    const float* beta1  = (const float*)d_in[14];
    const float* alpha2 = (const float*)d_in[15];
    const float* beta2  = (const float*)d_in[16];
    const int*   mask   = (const int*)d_in[17];

    float *tmp, *x1;
    cudaGetSymbolAddress((void**)&tmp, g_tmp);
    cudaGetSymbolAddress((void**)&x1,  g_x1);

    __half *xh, *qkvh, *ctxh, *x1h, *ff1h;
    cudaGetSymbolAddress((void**)&xh,   g_xh);
    cudaGetSymbolAddress((void**)&qkvh, g_qkvh);
    cudaGetSymbolAddress((void**)&ctxh, g_ctxh);
    cudaGetSymbolAddress((void**)&x1h,  g_x1h);
    cudaGetSymbolAddress((void**)&ff1h, g_ff1h);

    __half *wqkv, *woh, *w1h, *w2h;
    float  *bqkv;
    cudaGetSymbolAddress((void**)&wqkv, g_wqkv);
    cudaGetSymbolAddress((void**)&bqkv, g_bqkv);
    cudaGetSymbolAddress((void**)&woh,  g_woh);
    cudaGetSymbolAddress((void**)&w1h,  g_w1h);
    cudaGetSymbolAddress((void**)&w2h,  g_w2h);

    const size_t CS = (size_t)Mc * Dc;   // split-K output slice stride
    float* tmpA = tmp;
    float* tmpB = tmp + CS;

    int attn_smem = (int)sizeof(AttnSmem5);
    cudaFuncSetAttribute(attn_mma, cudaFuncAttributeMaxDynamicSharedMemorySize, attn_smem);
    cudaFuncSetAttribute(hgemm<0, 0>, cudaFuncAttributeMaxDynamicSharedMemorySize, HG_SMEM);
    cudaFuncSetAttribute(hgemm<0, 2>, cudaFuncAttributeMaxDynamicSharedMemorySize, HG_SMEM);
    cudaFuncSetAttribute(hgemm<1, 2>, cudaFuncAttributeMaxDynamicSharedMemorySize, HG_SMEM);

    dim3 blk(256);

    // 1. all conversions in one launch
    cvt_all<<<CB_TOTAL, blk>>>(wq, wk, wv, wo, w1, w2, x, bq, bk, bv);

    // 2. fused QKV projection: one uniform GEMM, N=2304, 576 CTAs
    hgemm<0, 2><<<dim3(QKVW / 128, Mc / 128, 1), blk, HG_SMEM>>>(
        xh, wqkv, bqkv, nullptr, qkvh, QKVW, Dc, Dc, 0);

    // 3. flash attention (3-stage K/V ring)
    attn_mma<<<dim3(Sc / 128, Bc * Hc), blk, attn_smem>>>(mask);

    // 4. O-projection split-K x2 (raw partials), LN1 folds bias bo
    hgemm<0, 0><<<dim3(Dc / 128, Mc / 128, 2), blk, HG_SMEM>>>(
        ctxh, woh, nullptr, tmpA, nullptr, Dc, Dc / 2, Dc, CS);
    add_ln_kernel<1><<<Mc, blk>>>(x, tmpA, tmpB, bo, alpha1, beta1, x1, x1h);

    // 5. FFN
    hgemm<1, 2><<<dim3(DFFc / 128, Mc / 128, 1), blk, HG_SMEM>>>(
        x1h, w1h, b1, nullptr, ff1h, DFFc, Dc, Dc, 0);
    hgemm<0, 0><<<dim3(Dc / 128, Mc / 128, 2), blk, HG_SMEM>>>(
        ff1h, w2h, nullptr, tmpA, nullptr, Dc, DFFc / 2, DFFc, CS);
    add_ln_kernel<0><<<Mc, blk>>>(x1, tmpA, tmpB, b2, alpha2, beta2,
                                  (float*)d_out, nullptr);
}